// round 11
// baseline (speedup 1.0000x reference)
#include <cuda_runtime.h>
#include <math.h>

#define BD 512
#define B_ 2
#define LQ 2048
#define LK 4096
#define NH 8
#define DH 64
#define PQ 65   // smem pitch for 64-wide tiles (bank-conflict mitigation)

// Scratch (device globals: allocation-free per harness rules)
__device__ float g_qp[B_*LQ*BD];   // projected Q  [B, Lq, 512]
__device__ float g_kp[B_*LK*BD];   // projected K  [B, Lk, 512]
__device__ float g_vp[B_*LK*BD];   // projected V  [B, Lk, 512]
__device__ float g_at[B_*LQ*BD];   // attention out [B, Lq, H*Dh]

// C[M,512] = A[M,512] @ W[512,512]^T + bias   (M multiple of 128)
__global__ __launch_bounds__(256) void sgemm_bias(
    const float* __restrict__ A, const float* __restrict__ W,
    const float* __restrict__ bias, float* __restrict__ C)
{
    __shared__ float As[8][128];
    __shared__ float Bs[8][128];
    const int tid = threadIdx.x;
    const int tx = tid & 15, ty = tid >> 4;
    const int bm = blockIdx.y * 128;
    const int bn = blockIdx.x * 128;
    const int lr = tid >> 1;          // 0..127
    const int lc = (tid & 1) * 4;     // 0 or 4

    float acc[8][8];
    #pragma unroll
    for (int i = 0; i < 8; i++)
        #pragma unroll
        for (int j = 0; j < 8; j++) acc[i][j] = 0.f;

    const float* Aptr = A + (size_t)(bm + lr) * BD + lc;
    const float* Wptr = W + (size_t)(bn + lr) * BD + lc;

    for (int k0 = 0; k0 < BD; k0 += 8) {
        float4 a4 = *(const float4*)(Aptr + k0);
        float4 w4 = *(const float4*)(Wptr + k0);
        As[lc+0][lr] = a4.x; As[lc+1][lr] = a4.y; As[lc+2][lr] = a4.z; As[lc+3][lr] = a4.w;
        Bs[lc+0][lr] = w4.x; Bs[lc+1][lr] = w4.y; Bs[lc+2][lr] = w4.z; Bs[lc+3][lr] = w4.w;
        __syncthreads();
        #pragma unroll
        for (int kk = 0; kk < 8; kk++) {
            float a[8], b[8];
            *(float4*)&a[0] = *(const float4*)&As[kk][ty*4];
            *(float4*)&a[4] = *(const float4*)&As[kk][64 + ty*4];
            *(float4*)&b[0] = *(const float4*)&Bs[kk][tx*4];
            *(float4*)&b[4] = *(const float4*)&Bs[kk][64 + tx*4];
            #pragma unroll
            for (int i = 0; i < 8; i++)
                #pragma unroll
                for (int j = 0; j < 8; j++)
                    acc[i][j] = fmaf(a[i], b[j], acc[i][j]);
        }
        __syncthreads();
    }

    #pragma unroll
    for (int i = 0; i < 8; i++) {
        int row = bm + ((i < 4) ? (ty*4 + i) : (64 + ty*4 + (i - 4)));
        #pragma unroll
        for (int jh = 0; jh < 2; jh++) {
            int col = bn + jh*64 + tx*4;
            float4 v;
            v.x = acc[i][jh*4+0] + bias[col+0];
            v.y = acc[i][jh*4+1] + bias[col+1];
            v.z = acc[i][jh*4+2] + bias[col+2];
            v.w = acc[i][jh*4+3] + bias[col+3];
            *(float4*)(C + (size_t)row * BD + col) = v;
        }
    }
}

// Flash-attention over projected Q/K/V with gating + masking.
// Block: 64 q-rows of one (b,h). 256 threads as 16x16, 4x4 micro-tile each.
__global__ __launch_bounds__(256) void attn_kernel(
    const float* __restrict__ gate, const int* __restrict__ mask)
{
    extern __shared__ float sm[];
    float* Qs   = sm;                 // [64][PQ]
    float* KP   = sm + 64*PQ;         // [64][PQ]  K tile, reused as P tile
    float* Vs   = sm + 2*64*PQ;       // [64][PQ]
    float* bias = sm + 3*64*PQ;       // [64]

    const int tid = threadIdx.x;
    const int tx = tid & 15, ty = tid >> 4;
    const int q0 = blockIdx.x * 64;
    const int b  = blockIdx.y >> 3, h = blockIdx.y & 7;
    const int ty4 = ty * 4, tx4 = tx * 4;

    const float* qb = g_qp + (size_t)(b*LQ + q0) * BD + h*DH;
    const float* kb = g_kp + (size_t)b * LK * BD + h*DH;
    const float* vb = g_vp + (size_t)b * LK * BD + h*DH;
    const float* gb = gate + b * LK;
    const int*   mb = mask + b * LK;

    // Load Q tile (pre-scaled by 1/sqrt(Dh))
    for (int e = tid*4; e < 64*DH; e += 1024) {
        int r = e >> 6, d = e & 63;
        float4 v = *(const float4*)(qb + (size_t)r * BD + d);
        Qs[r*PQ+d+0] = v.x * 0.125f; Qs[r*PQ+d+1] = v.y * 0.125f;
        Qs[r*PQ+d+2] = v.z * 0.125f; Qs[r*PQ+d+3] = v.w * 0.125f;
    }

    float m[4], l[4], o[4][4];
    #pragma unroll
    for (int i = 0; i < 4; i++) {
        m[i] = -INFINITY; l[i] = 0.f;
        #pragma unroll
        for (int j = 0; j < 4; j++) o[i][j] = 0.f;
    }

    for (int k0 = 0; k0 < LK; k0 += 64) {
        __syncthreads();  // prior-iter reads of KP(P)/Vs done; Q store visible (iter 0)
        for (int e = tid*4; e < 64*DH; e += 1024) {
            int r = e >> 6, d = e & 63;
            float4 kk = *(const float4*)(kb + (size_t)(k0+r) * BD + d);
            KP[r*PQ+d+0] = kk.x; KP[r*PQ+d+1] = kk.y;
            KP[r*PQ+d+2] = kk.z; KP[r*PQ+d+3] = kk.w;
            float4 vv = *(const float4*)(vb + (size_t)(k0+r) * BD + d);
            Vs[r*PQ+d+0] = vv.x; Vs[r*PQ+d+1] = vv.y;
            Vs[r*PQ+d+2] = vv.z; Vs[r*PQ+d+3] = vv.w;
        }
        if (tid < 64) {
            float g = gb[k0 + tid];
            bias[tid] = mb[k0 + tid] ? __logf(fmaxf(g, 1e-6f)) : -1e30f;
        }
        __syncthreads();

        // S = (Q*scale) @ K^T
        float s[4][4];
        #pragma unroll
        for (int i = 0; i < 4; i++)
            #pragma unroll
            for (int j = 0; j < 4; j++) s[i][j] = 0.f;

        #pragma unroll 4
        for (int d = 0; d < DH; d++) {
            float a[4], bb[4];
            #pragma unroll
            for (int i = 0; i < 4; i++) a[i]  = Qs[(ty4+i)*PQ + d];
            #pragma unroll
            for (int j = 0; j < 4; j++) bb[j] = KP[(tx4+j)*PQ + d];
            #pragma unroll
            for (int i = 0; i < 4; i++)
                #pragma unroll
                for (int j = 0; j < 4; j++)
                    s[i][j] = fmaf(a[i], bb[j], s[i][j]);
        }

        // gate/mask bias + online softmax update
        #pragma unroll
        for (int i = 0; i < 4; i++) {
            #pragma unroll
            for (int j = 0; j < 4; j++) s[i][j] += bias[tx4 + j];
            float mx = fmaxf(fmaxf(s[i][0], s[i][1]), fmaxf(s[i][2], s[i][3]));
            #pragma unroll
            for (int off = 8; off > 0; off >>= 1)
                mx = fmaxf(mx, __shfl_xor_sync(0xffffffffu, mx, off, 16));
            float mn = fmaxf(m[i], mx);
            float rs = 0.f;
            #pragma unroll
            for (int j = 0; j < 4; j++) { s[i][j] = __expf(s[i][j] - mn); rs += s[i][j]; }
            #pragma unroll
            for (int off = 8; off > 0; off >>= 1)
                rs += __shfl_xor_sync(0xffffffffu, rs, off, 16);
            float f = __expf(m[i] - mn);
            l[i] = l[i] * f + rs;
            m[i] = mn;
            #pragma unroll
            for (int j = 0; j < 4; j++) o[i][j] *= f;
        }

        __syncthreads();  // everyone done reading KP as K
        #pragma unroll
        for (int i = 0; i < 4; i++)
            #pragma unroll
            for (int j = 0; j < 4; j++)
                KP[(ty4+i)*PQ + tx4 + j] = s[i][j];
        __syncthreads();

        // O += P @ V
        #pragma unroll 4
        for (int k = 0; k < 64; k++) {
            float a[4], bb[4];
            #pragma unroll
            for (int i = 0; i < 4; i++) a[i]  = KP[(ty4+i)*PQ + k];
            #pragma unroll
            for (int j = 0; j < 4; j++) bb[j] = Vs[k*PQ + tx4 + j];
            #pragma unroll
            for (int i = 0; i < 4; i++)
                #pragma unroll
                for (int j = 0; j < 4; j++)
                    o[i][j] = fmaf(a[i], bb[j], o[i][j]);
        }
    }

    // epilogue: normalize and write [B, Lq, H*Dh]
    float* ob = g_at + (size_t)(b*LQ + q0) * BD + h*DH;
    #pragma unroll
    for (int i = 0; i < 4; i++) {
        float inv = 1.f / l[i];
        float4 v;
        v.x = o[i][0]*inv; v.y = o[i][1]*inv; v.z = o[i][2]*inv; v.w = o[i][3]*inv;
        *(float4*)(ob + (size_t)(ty4+i) * BD + tx4) = v;
    }
}

extern "C" void kernel_launch(void* const* d_in, const int* in_sizes, int n_in,
                              void* d_out, int out_size)
{
    const float* q    = (const float*)d_in[0];
    const float* kv   = (const float*)d_in[1];
    const float* gate = (const float*)d_in[2];
    const int*   msk  = (const int*)  d_in[3];
    const float* Wq   = (const float*)d_in[4];
    const float* bq   = (const float*)d_in[5];
    const float* Wk   = (const float*)d_in[6];
    const float* bk   = (const float*)d_in[7];
    const float* Wv   = (const float*)d_in[8];
    const float* bv   = (const float*)d_in[9];
    const float* Wo   = (const float*)d_in[10];
    const float* bo   = (const float*)d_in[11];
    float* out = (float*)d_out;

    float *qp, *kp, *vp, *at;
    cudaGetSymbolAddress((void**)&qp, g_qp);
    cudaGetSymbolAddress((void**)&kp, g_kp);
    cudaGetSymbolAddress((void**)&vp, g_vp);
    cudaGetSymbolAddress((void**)&at, g_at);

    // Projections
    sgemm_bias<<<dim3(4, (B_*LQ)/128), 256>>>(q,  Wq, bq, qp);
    sgemm_bias<<<dim3(4, (B_*LK)/128), 256>>>(kv, Wk, bk, kp);
    sgemm_bias<<<dim3(4, (B_*LK)/128), 256>>>(kv, Wv, bv, vp);

    // Attention
    int smem = (3*64*PQ + 64) * (int)sizeof(float);  // 50176 B
    cudaFuncSetAttribute(attn_kernel, cudaFuncAttributeMaxDynamicSharedMemorySize, smem);
    attn_kernel<<<dim3(LQ/64, B_*NH), 256, smem>>>(gate, msk);

    // Output projection
    sgemm_bias<<<dim3(4, (B_*LQ)/128), 256>>>(at, Wo, bo, out);
}

// round 12
// speedup vs baseline: 1.0003x; 1.0003x over previous
#include <cuda_runtime.h>
#include <math.h>

#define BD 512
#define B_ 2
#define LQ 2048
#define LK 4096
#define NH 8
#define DH 64
#define PQ 65   // smem pitch for 64-wide tiles (bank-conflict mitigation)

// Scratch (device globals: allocation-free per harness rules)
__device__ float g_qp[B_*LQ*BD];   // projected Q  [B, Lq, 512]
__device__ float g_kp[B_*LK*BD];   // projected K  [B, Lk, 512]
__device__ float g_vp[B_*LK*BD];   // projected V  [B, Lk, 512]
__device__ float g_at[B_*LQ*BD];   // attention out [B, Lq, H*Dh]

// C[M,512] = A[M,512] @ W[512,512]^T + bias   (M multiple of 128)
__global__ __launch_bounds__(256) void sgemm_bias(
    const float* __restrict__ A, const float* __restrict__ W,
    const float* __restrict__ bias, float* __restrict__ C)
{
    __shared__ float As[8][128];
    __shared__ float Bs[8][128];
    const int tid = threadIdx.x;
    const int tx = tid & 15, ty = tid >> 4;
    const int bm = blockIdx.y * 128;
    const int bn = blockIdx.x * 128;
    const int lr = tid >> 1;          // 0..127
    const int lc = (tid & 1) * 4;     // 0 or 4

    float acc[8][8];
    #pragma unroll
    for (int i = 0; i < 8; i++)
        #pragma unroll
        for (int j = 0; j < 8; j++) acc[i][j] = 0.f;

    const float* Aptr = A + (size_t)(bm + lr) * BD + lc;
    const float* Wptr = W + (size_t)(bn + lr) * BD + lc;

    for (int k0 = 0; k0 < BD; k0 += 8) {
        float4 a4 = *(const float4*)(Aptr + k0);
        float4 w4 = *(const float4*)(Wptr + k0);
        As[lc+0][lr] = a4.x; As[lc+1][lr] = a4.y; As[lc+2][lr] = a4.z; As[lc+3][lr] = a4.w;
        Bs[lc+0][lr] = w4.x; Bs[lc+1][lr] = w4.y; Bs[lc+2][lr] = w4.z; Bs[lc+3][lr] = w4.w;
        __syncthreads();
        #pragma unroll
        for (int kk = 0; kk < 8; kk++) {
            float a[8], b[8];
            *(float4*)&a[0] = *(const float4*)&As[kk][ty*4];
            *(float4*)&a[4] = *(const float4*)&As[kk][64 + ty*4];
            *(float4*)&b[0] = *(const float4*)&Bs[kk][tx*4];
            *(float4*)&b[4] = *(const float4*)&Bs[kk][64 + tx*4];
            #pragma unroll
            for (int i = 0; i < 8; i++)
                #pragma unroll
                for (int j = 0; j < 8; j++)
                    acc[i][j] = fmaf(a[i], b[j], acc[i][j]);
        }
        __syncthreads();
    }

    #pragma unroll
    for (int i = 0; i < 8; i++) {
        int row = bm + ((i < 4) ? (ty*4 + i) : (64 + ty*4 + (i - 4)));
        #pragma unroll
        for (int jh = 0; jh < 2; jh++) {
            int col = bn + jh*64 + tx*4;
            float4 v;
            v.x = acc[i][jh*4+0] + bias[col+0];
            v.y = acc[i][jh*4+1] + bias[col+1];
            v.z = acc[i][jh*4+2] + bias[col+2];
            v.w = acc[i][jh*4+3] + bias[col+3];
            *(float4*)(C + (size_t)row * BD + col) = v;
        }
    }
}

// Flash-attention over projected Q/K/V with gating + masking.
// Block: 64 q-rows of one (b,h). 256 threads as 16x16, 4x4 micro-tile each.
__global__ __launch_bounds__(256) void attn_kernel(
    const float* __restrict__ gate, const int* __restrict__ mask)
{
    extern __shared__ float sm[];
    float* Qs   = sm;                 // [64][PQ]
    float* KP   = sm + 64*PQ;         // [64][PQ]  K tile, reused as P tile
    float* Vs   = sm + 2*64*PQ;       // [64][PQ]
    float* bias = sm + 3*64*PQ;       // [64]

    const int tid = threadIdx.x;
    const int tx = tid & 15, ty = tid >> 4;
    const int q0 = blockIdx.x * 64;
    const int b  = blockIdx.y >> 3, h = blockIdx.y & 7;
    const int ty4 = ty * 4, tx4 = tx * 4;

    const float* qb = g_qp + (size_t)(b*LQ + q0) * BD + h*DH;
    const float* kb = g_kp + (size_t)b * LK * BD + h*DH;
    const float* vb = g_vp + (size_t)b * LK * BD + h*DH;
    const float* gb = gate + b * LK;
    const int*   mb = mask + b * LK;

    // Load Q tile (pre-scaled by 1/sqrt(Dh))
    for (int e = tid*4; e < 64*DH; e += 1024) {
        int r = e >> 6, d = e & 63;
        float4 v = *(const float4*)(qb + (size_t)r * BD + d);
        Qs[r*PQ+d+0] = v.x * 0.125f; Qs[r*PQ+d+1] = v.y * 0.125f;
        Qs[r*PQ+d+2] = v.z * 0.125f; Qs[r*PQ+d+3] = v.w * 0.125f;
    }

    float m[4], l[4], o[4][4];
    #pragma unroll
    for (int i = 0; i < 4; i++) {
        m[i] = -INFINITY; l[i] = 0.f;
        #pragma unroll
        for (int j = 0; j < 4; j++) o[i][j] = 0.f;
    }

    for (int k0 = 0; k0 < LK; k0 += 64) {
        __syncthreads();  // prior-iter reads of KP(P)/Vs done; Q store visible (iter 0)
        for (int e = tid*4; e < 64*DH; e += 1024) {
            int r = e >> 6, d = e & 63;
            float4 kk = *(const float4*)(kb + (size_t)(k0+r) * BD + d);
            KP[r*PQ+d+0] = kk.x; KP[r*PQ+d+1] = kk.y;
            KP[r*PQ+d+2] = kk.z; KP[r*PQ+d+3] = kk.w;
            float4 vv = *(const float4*)(vb + (size_t)(k0+r) * BD + d);
            Vs[r*PQ+d+0] = vv.x; Vs[r*PQ+d+1] = vv.y;
            Vs[r*PQ+d+2] = vv.z; Vs[r*PQ+d+3] = vv.w;
        }
        if (tid < 64) {
            float g = gb[k0 + tid];
            bias[tid] = mb[k0 + tid] ? __logf(fmaxf(g, 1e-6f)) : -1e30f;
        }
        __syncthreads();

        // S = (Q*scale) @ K^T
        float s[4][4];
        #pragma unroll
        for (int i = 0; i < 4; i++)
            #pragma unroll
            for (int j = 0; j < 4; j++) s[i][j] = 0.f;

        #pragma unroll 4
        for (int d = 0; d < DH; d++) {
            float a[4], bb[4];
            #pragma unroll
            for (int i = 0; i < 4; i++) a[i]  = Qs[(ty4+i)*PQ + d];
            #pragma unroll
            for (int j = 0; j < 4; j++) bb[j] = KP[(tx4+j)*PQ + d];
            #pragma unroll
            for (int i = 0; i < 4; i++)
                #pragma unroll
                for (int j = 0; j < 4; j++)
                    s[i][j] = fmaf(a[i], bb[j], s[i][j]);
        }

        // gate/mask bias + online softmax update
        #pragma unroll
        for (int i = 0; i < 4; i++) {
            #pragma unroll
            for (int j = 0; j < 4; j++) s[i][j] += bias[tx4 + j];
            float mx = fmaxf(fmaxf(s[i][0], s[i][1]), fmaxf(s[i][2], s[i][3]));
            #pragma unroll
            for (int off = 8; off > 0; off >>= 1)
                mx = fmaxf(mx, __shfl_xor_sync(0xffffffffu, mx, off, 16));
            float mn = fmaxf(m[i], mx);
            float rs = 0.f;
            #pragma unroll
            for (int j = 0; j < 4; j++) { s[i][j] = __expf(s[i][j] - mn); rs += s[i][j]; }
            #pragma unroll
            for (int off = 8; off > 0; off >>= 1)
                rs += __shfl_xor_sync(0xffffffffu, rs, off, 16);
            float f = __expf(m[i] - mn);
            l[i] = l[i] * f + rs;
            m[i] = mn;
            #pragma unroll
            for (int j = 0; j < 4; j++) o[i][j] *= f;
        }

        __syncthreads();  // everyone done reading KP as K
        #pragma unroll
        for (int i = 0; i < 4; i++)
            #pragma unroll
            for (int j = 0; j < 4; j++)
                KP[(ty4+i)*PQ + tx4 + j] = s[i][j];
        __syncthreads();

        // O += P @ V
        #pragma unroll 4
        for (int k = 0; k < 64; k++) {
            float a[4], bb[4];
            #pragma unroll
            for (int i = 0; i < 4; i++) a[i]  = KP[(ty4+i)*PQ + k];
            #pragma unroll
            for (int j = 0; j < 4; j++) bb[j] = Vs[k*PQ + tx4 + j];
            #pragma unroll
            for (int i = 0; i < 4; i++)
                #pragma unroll
                for (int j = 0; j < 4; j++)
                    o[i][j] = fmaf(a[i], bb[j], o[i][j]);
        }
    }

    // epilogue: normalize and write [B, Lq, H*Dh]
    float* ob = g_at + (size_t)(b*LQ + q0) * BD + h*DH;
    #pragma unroll
    for (int i = 0; i < 4; i++) {
        float inv = 1.f / l[i];
        float4 v;
        v.x = o[i][0]*inv; v.y = o[i][1]*inv; v.z = o[i][2]*inv; v.w = o[i][3]*inv;
        *(float4*)(ob + (size_t)(ty4+i) * BD + tx4) = v;
    }
}

extern "C" void kernel_launch(void* const* d_in, const int* in_sizes, int n_in,
                              void* d_out, int out_size)
{
    const float* q    = (const float*)d_in[0];
    const float* kv   = (const float*)d_in[1];
    const float* gate = (const float*)d_in[2];
    const int*   msk  = (const int*)  d_in[3];
    const float* Wq   = (const float*)d_in[4];
    const float* bq   = (const float*)d_in[5];
    const float* Wk   = (const float*)d_in[6];
    const float* bk   = (const float*)d_in[7];
    const float* Wv   = (const float*)d_in[8];
    const float* bv   = (const float*)d_in[9];
    const float* Wo   = (const float*)d_in[10];
    const float* bo   = (const float*)d_in[11];
    float* out = (float*)d_out;

    float *qp, *kp, *vp, *at;
    cudaGetSymbolAddress((void**)&qp, g_qp);
    cudaGetSymbolAddress((void**)&kp, g_kp);
    cudaGetSymbolAddress((void**)&vp, g_vp);
    cudaGetSymbolAddress((void**)&at, g_at);

    // Projections
    sgemm_bias<<<dim3(4, (B_*LQ)/128), 256>>>(q,  Wq, bq, qp);
    sgemm_bias<<<dim3(4, (B_*LK)/128), 256>>>(kv, Wk, bk, kp);
    sgemm_bias<<<dim3(4, (B_*LK)/128), 256>>>(kv, Wv, bv, vp);

    // Attention
    int smem = (3*64*PQ + 64) * (int)sizeof(float);  // 50176 B
    cudaFuncSetAttribute(attn_kernel, cudaFuncAttributeMaxDynamicSharedMemorySize, smem);
    attn_kernel<<<dim3(LQ/64, B_*NH), 256, smem>>>(gate, msk);

    // Output projection
    sgemm_bias<<<dim3(4, (B_*LQ)/128), 256>>>(at, Wo, bo, out);
}

// round 13
// speedup vs baseline: 1.0006x; 1.0003x over previous
#include <cuda_runtime.h>
#include <math.h>

#define BD 512
#define B_ 2
#define LQ 2048
#define LK 4096
#define NH 8
#define DH 64
#define PQ 65   // smem pitch for 64-wide tiles (bank-conflict mitigation)

// Scratch (device globals: allocation-free per harness rules)
__device__ float g_qp[B_*LQ*BD];   // projected Q  [B, Lq, 512]
__device__ float g_kp[B_*LK*BD];   // projected K  [B, Lk, 512]
__device__ float g_vp[B_*LK*BD];   // projected V  [B, Lk, 512]
__device__ float g_at[B_*LQ*BD];   // attention out [B, Lq, H*Dh]

// C[M,512] = A[M,512] @ W[512,512]^T + bias   (M multiple of 128)
__global__ __launch_bounds__(256) void sgemm_bias(
    const float* __restrict__ A, const float* __restrict__ W,
    const float* __restrict__ bias, float* __restrict__ C)
{
    __shared__ float As[8][128];
    __shared__ float Bs[8][128];
    const int tid = threadIdx.x;
    const int tx = tid & 15, ty = tid >> 4;
    const int bm = blockIdx.y * 128;
    const int bn = blockIdx.x * 128;
    const int lr = tid >> 1;          // 0..127
    const int lc = (tid & 1) * 4;     // 0 or 4

    float acc[8][8];
    #pragma unroll
    for (int i = 0; i < 8; i++)
        #pragma unroll
        for (int j = 0; j < 8; j++) acc[i][j] = 0.f;

    const float* Aptr = A + (size_t)(bm + lr) * BD + lc;
    const float* Wptr = W + (size_t)(bn + lr) * BD + lc;

    for (int k0 = 0; k0 < BD; k0 += 8) {
        float4 a4 = *(const float4*)(Aptr + k0);
        float4 w4 = *(const float4*)(Wptr + k0);
        As[lc+0][lr] = a4.x; As[lc+1][lr] = a4.y; As[lc+2][lr] = a4.z; As[lc+3][lr] = a4.w;
        Bs[lc+0][lr] = w4.x; Bs[lc+1][lr] = w4.y; Bs[lc+2][lr] = w4.z; Bs[lc+3][lr] = w4.w;
        __syncthreads();
        #pragma unroll
        for (int kk = 0; kk < 8; kk++) {
            float a[8], b[8];
            *(float4*)&a[0] = *(const float4*)&As[kk][ty*4];
            *(float4*)&a[4] = *(const float4*)&As[kk][64 + ty*4];
            *(float4*)&b[0] = *(const float4*)&Bs[kk][tx*4];
            *(float4*)&b[4] = *(const float4*)&Bs[kk][64 + tx*4];
            #pragma unroll
            for (int i = 0; i < 8; i++)
                #pragma unroll
                for (int j = 0; j < 8; j++)
                    acc[i][j] = fmaf(a[i], b[j], acc[i][j]);
        }
        __syncthreads();
    }

    #pragma unroll
    for (int i = 0; i < 8; i++) {
        int row = bm + ((i < 4) ? (ty*4 + i) : (64 + ty*4 + (i - 4)));
        #pragma unroll
        for (int jh = 0; jh < 2; jh++) {
            int col = bn + jh*64 + tx*4;
            float4 v;
            v.x = acc[i][jh*4+0] + bias[col+0];
            v.y = acc[i][jh*4+1] + bias[col+1];
            v.z = acc[i][jh*4+2] + bias[col+2];
            v.w = acc[i][jh*4+3] + bias[col+3];
            *(float4*)(C + (size_t)row * BD + col) = v;
        }
    }
}

// Flash-attention over projected Q/K/V with gating + masking.
// Block: 64 q-rows of one (b,h). 256 threads as 16x16, 4x4 micro-tile each.
__global__ __launch_bounds__(256) void attn_kernel(
    const float* __restrict__ gate, const int* __restrict__ mask)
{
    extern __shared__ float sm[];
    float* Qs   = sm;                 // [64][PQ]
    float* KP   = sm + 64*PQ;         // [64][PQ]  K tile, reused as P tile
    float* Vs   = sm + 2*64*PQ;       // [64][PQ]
    float* bias = sm + 3*64*PQ;       // [64]

    const int tid = threadIdx.x;
    const int tx = tid & 15, ty = tid >> 4;
    const int q0 = blockIdx.x * 64;
    const int b  = blockIdx.y >> 3, h = blockIdx.y & 7;
    const int ty4 = ty * 4, tx4 = tx * 4;

    const float* qb = g_qp + (size_t)(b*LQ + q0) * BD + h*DH;
    const float* kb = g_kp + (size_t)b * LK * BD + h*DH;
    const float* vb = g_vp + (size_t)b * LK * BD + h*DH;
    const float* gb = gate + b * LK;
    const int*   mb = mask + b * LK;

    // Load Q tile (pre-scaled by 1/sqrt(Dh))
    for (int e = tid*4; e < 64*DH; e += 1024) {
        int r = e >> 6, d = e & 63;
        float4 v = *(const float4*)(qb + (size_t)r * BD + d);
        Qs[r*PQ+d+0] = v.x * 0.125f; Qs[r*PQ+d+1] = v.y * 0.125f;
        Qs[r*PQ+d+2] = v.z * 0.125f; Qs[r*PQ+d+3] = v.w * 0.125f;
    }

    float m[4], l[4], o[4][4];
    #pragma unroll
    for (int i = 0; i < 4; i++) {
        m[i] = -INFINITY; l[i] = 0.f;
        #pragma unroll
        for (int j = 0; j < 4; j++) o[i][j] = 0.f;
    }

    for (int k0 = 0; k0 < LK; k0 += 64) {
        __syncthreads();  // prior-iter reads of KP(P)/Vs done; Q store visible (iter 0)
        for (int e = tid*4; e < 64*DH; e += 1024) {
            int r = e >> 6, d = e & 63;
            float4 kk = *(const float4*)(kb + (size_t)(k0+r) * BD + d);
            KP[r*PQ+d+0] = kk.x; KP[r*PQ+d+1] = kk.y;
            KP[r*PQ+d+2] = kk.z; KP[r*PQ+d+3] = kk.w;
            float4 vv = *(const float4*)(vb + (size_t)(k0+r) * BD + d);
            Vs[r*PQ+d+0] = vv.x; Vs[r*PQ+d+1] = vv.y;
            Vs[r*PQ+d+2] = vv.z; Vs[r*PQ+d+3] = vv.w;
        }
        if (tid < 64) {
            float g = gb[k0 + tid];
            bias[tid] = mb[k0 + tid] ? __logf(fmaxf(g, 1e-6f)) : -1e30f;
        }
        __syncthreads();

        // S = (Q*scale) @ K^T
        float s[4][4];
        #pragma unroll
        for (int i = 0; i < 4; i++)
            #pragma unroll
            for (int j = 0; j < 4; j++) s[i][j] = 0.f;

        #pragma unroll 4
        for (int d = 0; d < DH; d++) {
            float a[4], bb[4];
            #pragma unroll
            for (int i = 0; i < 4; i++) a[i]  = Qs[(ty4+i)*PQ + d];
            #pragma unroll
            for (int j = 0; j < 4; j++) bb[j] = KP[(tx4+j)*PQ + d];
            #pragma unroll
            for (int i = 0; i < 4; i++)
                #pragma unroll
                for (int j = 0; j < 4; j++)
                    s[i][j] = fmaf(a[i], bb[j], s[i][j]);
        }

        // gate/mask bias + online softmax update
        #pragma unroll
        for (int i = 0; i < 4; i++) {
            #pragma unroll
            for (int j = 0; j < 4; j++) s[i][j] += bias[tx4 + j];
            float mx = fmaxf(fmaxf(s[i][0], s[i][1]), fmaxf(s[i][2], s[i][3]));
            #pragma unroll
            for (int off = 8; off > 0; off >>= 1)
                mx = fmaxf(mx, __shfl_xor_sync(0xffffffffu, mx, off, 16));
            float mn = fmaxf(m[i], mx);
            float rs = 0.f;
            #pragma unroll
            for (int j = 0; j < 4; j++) { s[i][j] = __expf(s[i][j] - mn); rs += s[i][j]; }
            #pragma unroll
            for (int off = 8; off > 0; off >>= 1)
                rs += __shfl_xor_sync(0xffffffffu, rs, off, 16);
            float f = __expf(m[i] - mn);
            l[i] = l[i] * f + rs;
            m[i] = mn;
            #pragma unroll
            for (int j = 0; j < 4; j++) o[i][j] *= f;
        }

        __syncthreads();  // everyone done reading KP as K
        #pragma unroll
        for (int i = 0; i < 4; i++)
            #pragma unroll
            for (int j = 0; j < 4; j++)
                KP[(ty4+i)*PQ + tx4 + j] = s[i][j];
        __syncthreads();

        // O += P @ V
        #pragma unroll 4
        for (int k = 0; k < 64; k++) {
            float a[4], bb[4];
            #pragma unroll
            for (int i = 0; i < 4; i++) a[i]  = KP[(ty4+i)*PQ + k];
            #pragma unroll
            for (int j = 0; j < 4; j++) bb[j] = Vs[k*PQ + tx4 + j];
            #pragma unroll
            for (int i = 0; i < 4; i++)
                #pragma unroll
                for (int j = 0; j < 4; j++)
                    o[i][j] = fmaf(a[i], bb[j], o[i][j]);
        }
    }

    // epilogue: normalize and write [B, Lq, H*Dh]
    float* ob = g_at + (size_t)(b*LQ + q0) * BD + h*DH;
    #pragma unroll
    for (int i = 0; i < 4; i++) {
        float inv = 1.f / l[i];
        float4 v;
        v.x = o[i][0]*inv; v.y = o[i][1]*inv; v.z = o[i][2]*inv; v.w = o[i][3]*inv;
        *(float4*)(ob + (size_t)(ty4+i) * BD + tx4) = v;
    }
}

extern "C" void kernel_launch(void* const* d_in, const int* in_sizes, int n_in,
                              void* d_out, int out_size)
{
    const float* q    = (const float*)d_in[0];
    const float* kv   = (const float*)d_in[1];
    const float* gate = (const float*)d_in[2];
    const int*   msk  = (const int*)  d_in[3];
    const float* Wq   = (const float*)d_in[4];
    const float* bq   = (const float*)d_in[5];
    const float* Wk   = (const float*)d_in[6];
    const float* bk   = (const float*)d_in[7];
    const float* Wv   = (const float*)d_in[8];
    const float* bv   = (const float*)d_in[9];
    const float* Wo   = (const float*)d_in[10];
    const float* bo   = (const float*)d_in[11];
    float* out = (float*)d_out;

    float *qp, *kp, *vp, *at;
    cudaGetSymbolAddress((void**)&qp, g_qp);
    cudaGetSymbolAddress((void**)&kp, g_kp);
    cudaGetSymbolAddress((void**)&vp, g_vp);
    cudaGetSymbolAddress((void**)&at, g_at);

    // Projections
    sgemm_bias<<<dim3(4, (B_*LQ)/128), 256>>>(q,  Wq, bq, qp);
    sgemm_bias<<<dim3(4, (B_*LK)/128), 256>>>(kv, Wk, bk, kp);
    sgemm_bias<<<dim3(4, (B_*LK)/128), 256>>>(kv, Wv, bv, vp);

    // Attention
    int smem = (3*64*PQ + 64) * (int)sizeof(float);  // 50176 B
    cudaFuncSetAttribute(attn_kernel, cudaFuncAttributeMaxDynamicSharedMemorySize, smem);
    attn_kernel<<<dim3(LQ/64, B_*NH), 256, smem>>>(gate, msk);

    // Output projection
    sgemm_bias<<<dim3(4, (B_*LQ)/128), 256>>>(at, Wo, bo, out);
}

// round 14
// speedup vs baseline: 1.0012x; 1.0007x over previous
#include <cuda_runtime.h>
#include <math.h>

#define BD 512
#define B_ 2
#define LQ 2048
#define LK 4096
#define NH 8
#define DH 64
#define PQ 65   // smem pitch for 64-wide tiles (bank-conflict mitigation)

// Scratch (device globals: allocation-free per harness rules)
__device__ float g_qp[B_*LQ*BD];   // projected Q  [B, Lq, 512]
__device__ float g_kp[B_*LK*BD];   // projected K  [B, Lk, 512]
__device__ float g_vp[B_*LK*BD];   // projected V  [B, Lk, 512]
__device__ float g_at[B_*LQ*BD];   // attention out [B, Lq, H*Dh]

// C[M,512] = A[M,512] @ W[512,512]^T + bias   (M multiple of 128)
__global__ __launch_bounds__(256) void sgemm_bias(
    const float* __restrict__ A, const float* __restrict__ W,
    const float* __restrict__ bias, float* __restrict__ C)
{
    __shared__ float As[8][128];
    __shared__ float Bs[8][128];
    const int tid = threadIdx.x;
    const int tx = tid & 15, ty = tid >> 4;
    const int bm = blockIdx.y * 128;
    const int bn = blockIdx.x * 128;
    const int lr = tid >> 1;          // 0..127
    const int lc = (tid & 1) * 4;     // 0 or 4

    float acc[8][8];
    #pragma unroll
    for (int i = 0; i < 8; i++)
        #pragma unroll
        for (int j = 0; j < 8; j++) acc[i][j] = 0.f;

    const float* Aptr = A + (size_t)(bm + lr) * BD + lc;
    const float* Wptr = W + (size_t)(bn + lr) * BD + lc;

    for (int k0 = 0; k0 < BD; k0 += 8) {
        float4 a4 = *(const float4*)(Aptr + k0);
        float4 w4 = *(const float4*)(Wptr + k0);
        As[lc+0][lr] = a4.x; As[lc+1][lr] = a4.y; As[lc+2][lr] = a4.z; As[lc+3][lr] = a4.w;
        Bs[lc+0][lr] = w4.x; Bs[lc+1][lr] = w4.y; Bs[lc+2][lr] = w4.z; Bs[lc+3][lr] = w4.w;
        __syncthreads();
        #pragma unroll
        for (int kk = 0; kk < 8; kk++) {
            float a[8], b[8];
            *(float4*)&a[0] = *(const float4*)&As[kk][ty*4];
            *(float4*)&a[4] = *(const float4*)&As[kk][64 + ty*4];
            *(float4*)&b[0] = *(const float4*)&Bs[kk][tx*4];
            *(float4*)&b[4] = *(const float4*)&Bs[kk][64 + tx*4];
            #pragma unroll
            for (int i = 0; i < 8; i++)
                #pragma unroll
                for (int j = 0; j < 8; j++)
                    acc[i][j] = fmaf(a[i], b[j], acc[i][j]);
        }
        __syncthreads();
    }

    #pragma unroll
    for (int i = 0; i < 8; i++) {
        int row = bm + ((i < 4) ? (ty*4 + i) : (64 + ty*4 + (i - 4)));
        #pragma unroll
        for (int jh = 0; jh < 2; jh++) {
            int col = bn + jh*64 + tx*4;
            float4 v;
            v.x = acc[i][jh*4+0] + bias[col+0];
            v.y = acc[i][jh*4+1] + bias[col+1];
            v.z = acc[i][jh*4+2] + bias[col+2];
            v.w = acc[i][jh*4+3] + bias[col+3];
            *(float4*)(C + (size_t)row * BD + col) = v;
        }
    }
}

// Flash-attention over projected Q/K/V with gating + masking.
// Block: 64 q-rows of one (b,h). 256 threads as 16x16, 4x4 micro-tile each.
__global__ __launch_bounds__(256) void attn_kernel(
    const float* __restrict__ gate, const int* __restrict__ mask)
{
    extern __shared__ float sm[];
    float* Qs   = sm;                 // [64][PQ]
    float* KP   = sm + 64*PQ;         // [64][PQ]  K tile, reused as P tile
    float* Vs   = sm + 2*64*PQ;       // [64][PQ]
    float* bias = sm + 3*64*PQ;       // [64]

    const int tid = threadIdx.x;
    const int tx = tid & 15, ty = tid >> 4;
    const int q0 = blockIdx.x * 64;
    const int b  = blockIdx.y >> 3, h = blockIdx.y & 7;
    const int ty4 = ty * 4, tx4 = tx * 4;

    const float* qb = g_qp + (size_t)(b*LQ + q0) * BD + h*DH;
    const float* kb = g_kp + (size_t)b * LK * BD + h*DH;
    const float* vb = g_vp + (size_t)b * LK * BD + h*DH;
    const float* gb = gate + b * LK;
    const int*   mb = mask + b * LK;

    // Load Q tile (pre-scaled by 1/sqrt(Dh))
    for (int e = tid*4; e < 64*DH; e += 1024) {
        int r = e >> 6, d = e & 63;
        float4 v = *(const float4*)(qb + (size_t)r * BD + d);
        Qs[r*PQ+d+0] = v.x * 0.125f; Qs[r*PQ+d+1] = v.y * 0.125f;
        Qs[r*PQ+d+2] = v.z * 0.125f; Qs[r*PQ+d+3] = v.w * 0.125f;
    }

    float m[4], l[4], o[4][4];
    #pragma unroll
    for (int i = 0; i < 4; i++) {
        m[i] = -INFINITY; l[i] = 0.f;
        #pragma unroll
        for (int j = 0; j < 4; j++) o[i][j] = 0.f;
    }

    for (int k0 = 0; k0 < LK; k0 += 64) {
        __syncthreads();  // prior-iter reads of KP(P)/Vs done; Q store visible (iter 0)
        for (int e = tid*4; e < 64*DH; e += 1024) {
            int r = e >> 6, d = e & 63;
            float4 kk = *(const float4*)(kb + (size_t)(k0+r) * BD + d);
            KP[r*PQ+d+0] = kk.x; KP[r*PQ+d+1] = kk.y;
            KP[r*PQ+d+2] = kk.z; KP[r*PQ+d+3] = kk.w;
            float4 vv = *(const float4*)(vb + (size_t)(k0+r) * BD + d);
            Vs[r*PQ+d+0] = vv.x; Vs[r*PQ+d+1] = vv.y;
            Vs[r*PQ+d+2] = vv.z; Vs[r*PQ+d+3] = vv.w;
        }
        if (tid < 64) {
            float g = gb[k0 + tid];
            bias[tid] = mb[k0 + tid] ? __logf(fmaxf(g, 1e-6f)) : -1e30f;
        }
        __syncthreads();

        // S = (Q*scale) @ K^T
        float s[4][4];
        #pragma unroll
        for (int i = 0; i < 4; i++)
            #pragma unroll
            for (int j = 0; j < 4; j++) s[i][j] = 0.f;

        #pragma unroll 4
        for (int d = 0; d < DH; d++) {
            float a[4], bb[4];
            #pragma unroll
            for (int i = 0; i < 4; i++) a[i]  = Qs[(ty4+i)*PQ + d];
            #pragma unroll
            for (int j = 0; j < 4; j++) bb[j] = KP[(tx4+j)*PQ + d];
            #pragma unroll
            for (int i = 0; i < 4; i++)
                #pragma unroll
                for (int j = 0; j < 4; j++)
                    s[i][j] = fmaf(a[i], bb[j], s[i][j]);
        }

        // gate/mask bias + online softmax update
        #pragma unroll
        for (int i = 0; i < 4; i++) {
            #pragma unroll
            for (int j = 0; j < 4; j++) s[i][j] += bias[tx4 + j];
            float mx = fmaxf(fmaxf(s[i][0], s[i][1]), fmaxf(s[i][2], s[i][3]));
            #pragma unroll
            for (int off = 8; off > 0; off >>= 1)
                mx = fmaxf(mx, __shfl_xor_sync(0xffffffffu, mx, off, 16));
            float mn = fmaxf(m[i], mx);
            float rs = 0.f;
            #pragma unroll
            for (int j = 0; j < 4; j++) { s[i][j] = __expf(s[i][j] - mn); rs += s[i][j]; }
            #pragma unroll
            for (int off = 8; off > 0; off >>= 1)
                rs += __shfl_xor_sync(0xffffffffu, rs, off, 16);
            float f = __expf(m[i] - mn);
            l[i] = l[i] * f + rs;
            m[i] = mn;
            #pragma unroll
            for (int j = 0; j < 4; j++) o[i][j] *= f;
        }

        __syncthreads();  // everyone done reading KP as K
        #pragma unroll
        for (int i = 0; i < 4; i++)
            #pragma unroll
            for (int j = 0; j < 4; j++)
                KP[(ty4+i)*PQ + tx4 + j] = s[i][j];
        __syncthreads();

        // O += P @ V
        #pragma unroll 4
        for (int k = 0; k < 64; k++) {
            float a[4], bb[4];
            #pragma unroll
            for (int i = 0; i < 4; i++) a[i]  = KP[(ty4+i)*PQ + k];
            #pragma unroll
            for (int j = 0; j < 4; j++) bb[j] = Vs[k*PQ + tx4 + j];
            #pragma unroll
            for (int i = 0; i < 4; i++)
                #pragma unroll
                for (int j = 0; j < 4; j++)
                    o[i][j] = fmaf(a[i], bb[j], o[i][j]);
        }
    }

    // epilogue: normalize and write [B, Lq, H*Dh]
    float* ob = g_at + (size_t)(b*LQ + q0) * BD + h*DH;
    #pragma unroll
    for (int i = 0; i < 4; i++) {
        float inv = 1.f / l[i];
        float4 v;
        v.x = o[i][0]*inv; v.y = o[i][1]*inv; v.z = o[i][2]*inv; v.w = o[i][3]*inv;
        *(float4*)(ob + (size_t)(ty4+i) * BD + tx4) = v;
    }
}

extern "C" void kernel_launch(void* const* d_in, const int* in_sizes, int n_in,
                              void* d_out, int out_size)
{
    const float* q    = (const float*)d_in[0];
    const float* kv   = (const float*)d_in[1];
    const float* gate = (const float*)d_in[2];
    const int*   msk  = (const int*)  d_in[3];
    const float* Wq   = (const float*)d_in[4];
    const float* bq   = (const float*)d_in[5];
    const float* Wk   = (const float*)d_in[6];
    const float* bk   = (const float*)d_in[7];
    const float* Wv   = (const float*)d_in[8];
    const float* bv   = (const float*)d_in[9];
    const float* Wo   = (const float*)d_in[10];
    const float* bo   = (const float*)d_in[11];
    float* out = (float*)d_out;

    float *qp, *kp, *vp, *at;
    cudaGetSymbolAddress((void**)&qp, g_qp);
    cudaGetSymbolAddress((void**)&kp, g_kp);
    cudaGetSymbolAddress((void**)&vp, g_vp);
    cudaGetSymbolAddress((void**)&at, g_at);

    // Projections
    sgemm_bias<<<dim3(4, (B_*LQ)/128), 256>>>(q,  Wq, bq, qp);
    sgemm_bias<<<dim3(4, (B_*LK)/128), 256>>>(kv, Wk, bk, kp);
    sgemm_bias<<<dim3(4, (B_*LK)/128), 256>>>(kv, Wv, bv, vp);

    // Attention
    int smem = (3*64*PQ + 64) * (int)sizeof(float);  // 50176 B
    cudaFuncSetAttribute(attn_kernel, cudaFuncAttributeMaxDynamicSharedMemorySize, smem);
    attn_kernel<<<dim3(LQ/64, B_*NH), 256, smem>>>(gate, msk);

    // Output projection
    sgemm_bias<<<dim3(4, (B_*LQ)/128), 256>>>(at, Wo, bo, out);
}